// round 4
// baseline (speedup 1.0000x reference)
#include <cuda_runtime.h>
#include <cuda_bf16.h>
#include <cstdint>

#define B_ 16
#define P_ 16
#define I_ 16
#define L_ 64
#define D_ 128
#define F_ 128
#define C_ 1024
#define BPI 4096
#define BP 256
#define NEG (-1000000000.0f)
#define INV_SQRT_F 0.08838834764831845f

// ---------------- scratch (no allocations allowed) ----------------
__device__ float d_meanx[BPI * D_];       // (B,P,I,D) masked means
__device__ float d_WcT[D_ * 384];         // folded qkv weight, transposed [d][t]
__device__ float d_bc[384];               // folded qkv bias
__device__ float d_meta[BP * F_];         // (B,P,F)
__device__ float d_base[B_];              // per-b score base
__device__ float d_scores[B_ * P_ * C_];  // raw masked logits

// ---------------- Kernel A: masked mean over L ----------------
// block = one (b,p,i); 128 threads = 4 warps; warp w handles rows l = w, w+4, ...
// each lane loads a float4 => one warp covers a full 512B row (perfectly coalesced)
__global__ void k_mean(const float* __restrict__ pe, const int* __restrict__ plen) {
    int bpi = blockIdx.x;
    int len = plen[bpi];
    int warp = threadIdx.x >> 5, lane = threadIdx.x & 31;
    const float4* base = (const float4*)pe + (size_t)bpi * (L_ * 32);
    float4 acc = make_float4(0.f, 0.f, 0.f, 0.f);
    for (int l = warp; l < len; l += 4) {
        float4 v = base[l * 32 + lane];
        acc.x += v.x; acc.y += v.y; acc.z += v.z; acc.w += v.w;
    }
    __shared__ float4 sred[128];
    sred[threadIdx.x] = acc;
    __syncthreads();
    if (warp == 0) {
        float4 a = sred[lane], b = sred[32 + lane], c = sred[64 + lane], d = sred[96 + lane];
        float inv = 1.0f / (float)len;
        float4 r;
        r.x = (a.x + b.x + c.x + d.x) * inv;
        r.y = (a.y + b.y + c.y + d.y) * inv;
        r.z = (a.z + b.z + c.z + d.z) * inv;
        r.w = (a.w + b.w + c.w + d.w) * inv;
        ((float4*)d_meanx)[(size_t)bpi * 32 + lane] = r;
    }
}

// ---------------- Kernel B: fold conv into pia_in ----------------
// Wc[t,d] = sum_f pia_in_w[t,f] * conv_w[f,d]   (stored transposed [d][t])
// bc[t]   = pia_in_b[t] + sum_f pia_in_w[t,f] * conv_b[f]
__global__ void k_fold(const float* __restrict__ piw, const float* __restrict__ pib,
                       const float* __restrict__ cw, const float* __restrict__ cb) {
    int t = blockIdx.x;      // 0..383
    int d = threadIdx.x;     // 0..127
    float s = 0.f;
    #pragma unroll 4
    for (int f = 0; f < F_; f++) s += piw[t * F_ + f] * cw[f * D_ + d];
    d_WcT[d * 384 + t] = s;
    __shared__ float sb[128];
    sb[d] = piw[t * F_ + d] * cb[d];
    __syncthreads();
    for (int off = 64; off > 0; off >>= 1) {
        if (d < off) sb[d] += sb[d + off];
        __syncthreads();
    }
    if (d == 0) d_bc[t] = pib[t] + sb[0];
}

// ---------------- Kernel C: PIA attention per (b,p), fused conv, mean-folded ----------------
__global__ void k_pia(const float* __restrict__ pow_, const float* __restrict__ pob) {
    int bp = blockIdx.x;
    int t = threadIdx.x;  // 0..383
    __shared__ float xs[I_ * D_];
    __shared__ float qs[I_ * 132], ks[I_ * 132], vs[I_ * 132];
    __shared__ float attn[I_ * I_];
    __shared__ float amean[I_];
    __shared__ float vmean[D_];

    const float* xg = d_meanx + (size_t)bp * I_ * D_;
    for (int idx = t; idx < I_ * D_; idx += 384) xs[idx] = xg[idx];
    __syncthreads();

    // qkv: thread t computes one of the 384 projection outputs for all 16 rows
    float acc[I_];
    #pragma unroll
    for (int i = 0; i < I_; i++) acc[i] = 0.f;
    for (int d = 0; d < D_; d++) {
        float w = d_WcT[d * 384 + t];  // coalesced across t
        #pragma unroll
        for (int i = 0; i < I_; i++) acc[i] += xs[i * D_ + d] * w;
    }
    {
        float b = d_bc[t];
        float* dst = (t < 128) ? qs : (t < 256 ? ks : vs);
        int f = t & 127;
        #pragma unroll
        for (int i = 0; i < I_; i++) dst[i * 132 + f] = acc[i] + b;
    }
    __syncthreads();

    // attention logits: 256 (i,j) pairs
    if (t < 256) {
        int i = t >> 4, j = t & 15;
        float s = 0.f;
        #pragma unroll 8
        for (int f = 0; f < D_; f++) s += qs[i * 132 + f] * ks[j * 132 + f];
        attn[t] = s * INV_SQRT_F;
    }
    __syncthreads();
    if (t < I_) {  // softmax row t
        float m = attn[t * 16];
        for (int j = 1; j < 16; j++) m = fmaxf(m, attn[t * 16 + j]);
        float sum = 0.f;
        for (int j = 0; j < 16; j++) { float e = __expf(attn[t * 16 + j] - m); attn[t * 16 + j] = e; sum += e; }
        float inv = 1.f / sum;
        for (int j = 0; j < 16; j++) attn[t * 16 + j] *= inv;
    }
    __syncthreads();
    if (t < I_) {  // column means of attn
        float s = 0.f;
        for (int i = 0; i < 16; i++) s += attn[i * 16 + t];
        amean[t] = s * (1.f / 16.f);
    }
    __syncthreads();
    if (t < D_) {
        float s = 0.f;
        #pragma unroll
        for (int j = 0; j < I_; j++) s += amean[j] * vs[j * 132 + t];
        vmean[t] = s;
    }
    __syncthreads();
    if (t < F_) {  // meta = vmean @ out_w^T + out_b
        float s = pob[t];
        #pragma unroll 4
        for (int f = 0; f < D_; f++) s += vmean[f] * pow_[t * D_ + f];
        d_meta[(size_t)bp * F_ + t] = s;
    }
}

// ---------------- Kernel D: MPA per b + v2 + score base ----------------
__global__ void k_mpa(const float* __restrict__ miw, const float* __restrict__ mib,
                      const float* __restrict__ mow, const float* __restrict__ mob,
                      const float* __restrict__ qiw, const float* __restrict__ qib,
                      const float* __restrict__ qow, const float* __restrict__ qob,
                      const float* __restrict__ query, const float* __restrict__ sw,
                      const float* __restrict__ sb) {
    int b = blockIdx.x;
    int t = threadIdx.x;  // 0..127
    __shared__ float xs[I_ * D_];
    __shared__ float qs[I_ * 132], ks[I_ * 132], vs[I_ * 132];
    __shared__ float attn[I_ * I_];
    __shared__ float amean[I_];
    __shared__ float vmean[D_], v1s[F_], mps[F_], t1s[F_], v2s[F_];
    __shared__ float red[128];

    const float* xg = d_meta + (size_t)b * I_ * D_;
    for (int idx = t; idx < I_ * D_; idx += 128) xs[idx] = xg[idx];
    __syncthreads();

    for (int part = 0; part < 3; part++) {
        const float* wrow = miw + (size_t)(part * F_ + t) * F_;
        float acc[I_];
        #pragma unroll
        for (int i = 0; i < I_; i++) acc[i] = 0.f;
        for (int d = 0; d < D_; d++) {
            float w = wrow[d];
            #pragma unroll
            for (int i = 0; i < I_; i++) acc[i] += xs[i * D_ + d] * w;
        }
        float bb = mib[part * F_ + t];
        float* dst = part == 0 ? qs : (part == 1 ? ks : vs);
        #pragma unroll
        for (int i = 0; i < I_; i++) dst[i * 132 + t] = acc[i] + bb;
    }
    __syncthreads();

    for (int pr = t; pr < 256; pr += 128) {
        int i = pr >> 4, j = pr & 15;
        float s = 0.f;
        #pragma unroll 8
        for (int f = 0; f < D_; f++) s += qs[i * 132 + f] * ks[j * 132 + f];
        attn[pr] = s * INV_SQRT_F;
    }
    __syncthreads();
    if (t < I_) {
        float m = attn[t * 16];
        for (int j = 1; j < 16; j++) m = fmaxf(m, attn[t * 16 + j]);
        float sum = 0.f;
        for (int j = 0; j < 16; j++) { float e = __expf(attn[t * 16 + j] - m); attn[t * 16 + j] = e; sum += e; }
        float inv = 1.f / sum;
        for (int j = 0; j < 16; j++) attn[t * 16 + j] *= inv;
    }
    __syncthreads();
    if (t < I_) {
        float s = 0.f;
        for (int i = 0; i < 16; i++) s += attn[i * 16 + t];
        amean[t] = s * (1.f / 16.f);
    }
    __syncthreads();
    {   // vmean and mean over P of meta
        float s = 0.f;
        #pragma unroll
        for (int j = 0; j < I_; j++) s += amean[j] * vs[j * 132 + t];
        vmean[t] = s;
        float sm = 0.f;
        #pragma unroll
        for (int i = 0; i < I_; i++) sm += xs[i * D_ + t];
        mps[t] = sm * (1.f / 16.f);
    }
    __syncthreads();
    {   // v1 = vmean @ mpa_out_w^T + b ; t1 = meanP @ qia_v_w^T + qia_v_b
        float s = mob[t];
        #pragma unroll 4
        for (int f = 0; f < D_; f++) s += vmean[f] * mow[t * D_ + f];
        v1s[t] = s;
        float s2 = qib[2 * F_ + t];
        const float* wrow = qiw + (size_t)(2 * F_ + t) * F_;
        #pragma unroll 4
        for (int f = 0; f < F_; f++) s2 += mps[f] * wrow[f];
        t1s[t] = s2;
    }
    __syncthreads();
    {   // v2 = t1 @ qia_out_w^T + b
        float s = qob[t];
        #pragma unroll 4
        for (int f = 0; f < F_; f++) s += t1s[f] * qow[t * F_ + f];
        v2s[t] = s;
    }
    __syncthreads();
    // base[b] = q.w0 + v1.w1 + v2.w2 + score_b
    float pb = query[b * D_ + t] * sw[t] + v1s[t] * sw[D_ + t] + v2s[t] * sw[D_ + F_ + t];
    red[t] = pb;
    __syncthreads();
    for (int off = 64; off > 0; off >>= 1) {
        if (t < off) red[t] += red[t + off];
        __syncthreads();
    }
    if (t == 0) d_base[b] = red[0] + sb[0];
}

// ---------------- Kernel F: candidate scores ----------------
// block = (b,p); 8 warps, warp = one candidate per iteration (float4 dot of 128)
__global__ void k_score(const float* __restrict__ cand, const int* __restrict__ clen,
                        const float* __restrict__ sw) {
    int bp = blockIdx.x;
    int b = bp >> 4;
    int warp = threadIdx.x >> 5, lane = threadIdx.x & 31;
    __shared__ float4 ws[32];
    __shared__ float sbase;
    if (threadIdx.x < 32) ws[threadIdx.x] = ((const float4*)(sw + D_ + 2 * F_))[threadIdx.x];
    if (threadIdx.x == 0) sbase = d_base[b];
    int len = clen[bp];
    __syncthreads();
    const float4* cbase = (const float4*)cand + (size_t)bp * C_ * 32;
    float4 w = ws[lane];
    float bse = sbase;
    for (int c = warp; c < C_; c += 8) {
        float4 v = cbase[c * 32 + lane];
        float s = v.x * w.x + v.y * w.y + v.z * w.z + v.w * w.w;
        #pragma unroll
        for (int off = 16; off; off >>= 1) s += __shfl_xor_sync(0xffffffffu, s, off);
        if (lane == 0) d_scores[(size_t)bp * C_ + c] = (c < len) ? (s + bse) : NEG;
    }
}

// ---------------- Kernel G: softmax over P*C per b ----------------
__global__ void k_softmax(float* __restrict__ out) {
    int b = blockIdx.x;
    const float* s = d_scores + (size_t)b * (P_ * C_);
    float* o = out + (size_t)b * (P_ * C_);
    int t = threadIdx.x;  // 0..1023
    __shared__ float red[1024];
    float m = -1e30f;
    for (int i = t; i < P_ * C_; i += 1024) m = fmaxf(m, s[i]);
    red[t] = m;
    __syncthreads();
    for (int off = 512; off > 0; off >>= 1) {
        if (t < off) red[t] = fmaxf(red[t], red[t + off]);
        __syncthreads();
    }
    float mx = red[0];
    __syncthreads();
    float sum = 0.f;
    for (int i = t; i < P_ * C_; i += 1024) sum += __expf(s[i] - mx);
    red[t] = sum;
    __syncthreads();
    for (int off = 512; off > 0; off >>= 1) {
        if (t < off) red[t] += red[t + off];
        __syncthreads();
    }
    float inv = 1.f / red[0];
    for (int i = t; i < P_ * C_; i += 1024) o[i] = __expf(s[i] - mx) * inv;
}

// ---------------- launch ----------------
extern "C" void kernel_launch(void* const* d_in, const int* in_sizes, int n_in,
                              void* d_out, int out_size) {
    const float* query    = (const float*)d_in[0];
    const float* path_emb = (const float*)d_in[1];
    const int*   path_len = (const int*)d_in[2];
    const float* cand_emb = (const float*)d_in[3];
    const int*   cand_len = (const int*)d_in[4];
    const float* conv_w   = (const float*)d_in[5];
    const float* conv_b   = (const float*)d_in[6];
    const float* pia_in_w = (const float*)d_in[7];
    const float* pia_in_b = (const float*)d_in[8];
    const float* pia_out_w= (const float*)d_in[9];
    const float* pia_out_b= (const float*)d_in[10];
    const float* mpa_in_w = (const float*)d_in[11];
    const float* mpa_in_b = (const float*)d_in[12];
    const float* mpa_out_w= (const float*)d_in[13];
    const float* mpa_out_b= (const float*)d_in[14];
    const float* qia_in_w = (const float*)d_in[15];
    const float* qia_in_b = (const float*)d_in[16];
    const float* qia_out_w= (const float*)d_in[17];
    const float* qia_out_b= (const float*)d_in[18];
    const float* score_w  = (const float*)d_in[19];
    const float* score_b  = (const float*)d_in[20];
    float* out = (float*)d_out;

    k_mean<<<BPI, 128>>>(path_emb, path_len);
    k_fold<<<384, 128>>>(pia_in_w, pia_in_b, conv_w, conv_b);
    k_pia<<<BP, 384>>>(pia_out_w, pia_out_b);
    k_mpa<<<B_, 128>>>(mpa_in_w, mpa_in_b, mpa_out_w, mpa_out_b,
                       qia_in_w, qia_in_b, qia_out_w, qia_out_b,
                       query, score_w, score_b);
    k_score<<<BP, 256>>>(cand_emb, cand_len, score_w);
    k_softmax<<<B_, 1024>>>(out);
}

// round 6
// speedup vs baseline: 1.0095x; 1.0095x over previous
#include <cuda_runtime.h>
#include <cuda_bf16.h>
#include <cstdint>

#define B_ 16
#define P_ 16
#define I_ 16
#define L_ 64
#define D_ 128
#define F_ 128
#define C_ 1024
#define BPI 4096
#define BP 256
#define NEG (-1000000000.0f)
#define INV_SQRT_F 0.08838834764831845f

// ---------------- scratch (no allocations allowed) ----------------
__device__ float d_meanx[BPI * D_];       // (B,P,I,D) masked means
__device__ float d_WcT[D_ * 384];         // folded qkv weight, transposed [d][t]
__device__ float d_bc[384];               // folded qkv bias
__device__ float d_meta[BP * F_];         // (B,P,F)
__device__ float d_base[B_];              // per-b score base
__device__ float d_scores[B_ * P_ * C_];  // raw masked logits

// ---------------- Kernel A: masked mean over L ----------------
// block = one (b,p,i); 128 threads = 4 warps; warp w handles rows l = w, w+4, ...
// each lane loads a float4 => one warp covers a full 512B row (perfectly coalesced)
__global__ void k_mean(const float* __restrict__ pe, const int* __restrict__ plen) {
    int bpi = blockIdx.x;
    int len = plen[bpi];
    int warp = threadIdx.x >> 5, lane = threadIdx.x & 31;
    const float4* base = (const float4*)pe + (size_t)bpi * (L_ * 32);
    float4 acc = make_float4(0.f, 0.f, 0.f, 0.f);
    for (int l = warp; l < len; l += 4) {
        float4 v = base[l * 32 + lane];
        acc.x += v.x; acc.y += v.y; acc.z += v.z; acc.w += v.w;
    }
    __shared__ float4 sred[128];
    sred[threadIdx.x] = acc;
    __syncthreads();
    if (warp == 0) {
        float4 a = sred[lane], b = sred[32 + lane], c = sred[64 + lane], d = sred[96 + lane];
        float inv = 1.0f / (float)len;
        float4 r;
        r.x = (a.x + b.x + c.x + d.x) * inv;
        r.y = (a.y + b.y + c.y + d.y) * inv;
        r.z = (a.z + b.z + c.z + d.z) * inv;
        r.w = (a.w + b.w + c.w + d.w) * inv;
        ((float4*)d_meanx)[(size_t)bpi * 32 + lane] = r;
    }
}

// ---------------- Kernel B: fold conv into pia_in ----------------
// Wc[t,d] = sum_f pia_in_w[t,f] * conv_w[f,d]   (stored transposed [d][t])
// bc[t]   = pia_in_b[t] + sum_f pia_in_w[t,f] * conv_b[f]
__global__ void k_fold(const float* __restrict__ piw, const float* __restrict__ pib,
                       const float* __restrict__ cw, const float* __restrict__ cb) {
    int t = blockIdx.x;      // 0..383
    int d = threadIdx.x;     // 0..127
    float s = 0.f;
    #pragma unroll 4
    for (int f = 0; f < F_; f++) s += piw[t * F_ + f] * cw[f * D_ + d];
    d_WcT[d * 384 + t] = s;
    __shared__ float sb[128];
    sb[d] = piw[t * F_ + d] * cb[d];
    __syncthreads();
    for (int off = 64; off > 0; off >>= 1) {
        if (d < off) sb[d] += sb[d + off];
        __syncthreads();
    }
    if (d == 0) d_bc[t] = pib[t] + sb[0];
}

// ---------------- Kernel C: PIA attention per (b,p), fused conv, mean-folded ----------------
__global__ void k_pia(const float* __restrict__ pow_, const float* __restrict__ pob) {
    int bp = blockIdx.x;
    int t = threadIdx.x;  // 0..383
    __shared__ float xs[I_ * D_];
    __shared__ float qs[I_ * 132], ks[I_ * 132], vs[I_ * 132];
    __shared__ float attn[I_ * I_];
    __shared__ float amean[I_];
    __shared__ float vmean[D_];

    const float* xg = d_meanx + (size_t)bp * I_ * D_;
    for (int idx = t; idx < I_ * D_; idx += 384) xs[idx] = xg[idx];
    __syncthreads();

    // qkv: thread t computes one of the 384 projection outputs for all 16 rows
    float acc[I_];
    #pragma unroll
    for (int i = 0; i < I_; i++) acc[i] = 0.f;
    for (int d = 0; d < D_; d++) {
        float w = d_WcT[d * 384 + t];  // coalesced across t
        #pragma unroll
        for (int i = 0; i < I_; i++) acc[i] += xs[i * D_ + d] * w;
    }
    {
        float b = d_bc[t];
        float* dst = (t < 128) ? qs : (t < 256 ? ks : vs);
        int f = t & 127;
        #pragma unroll
        for (int i = 0; i < I_; i++) dst[i * 132 + f] = acc[i] + b;
    }
    __syncthreads();

    // attention logits: 256 (i,j) pairs
    if (t < 256) {
        int i = t >> 4, j = t & 15;
        float s = 0.f;
        #pragma unroll 8
        for (int f = 0; f < D_; f++) s += qs[i * 132 + f] * ks[j * 132 + f];
        attn[t] = s * INV_SQRT_F;
    }
    __syncthreads();
    if (t < I_) {  // softmax row t
        float m = attn[t * 16];
        for (int j = 1; j < 16; j++) m = fmaxf(m, attn[t * 16 + j]);
        float sum = 0.f;
        for (int j = 0; j < 16; j++) { float e = __expf(attn[t * 16 + j] - m); attn[t * 16 + j] = e; sum += e; }
        float inv = 1.f / sum;
        for (int j = 0; j < 16; j++) attn[t * 16 + j] *= inv;
    }
    __syncthreads();
    if (t < I_) {  // column means of attn
        float s = 0.f;
        for (int i = 0; i < 16; i++) s += attn[i * 16 + t];
        amean[t] = s * (1.f / 16.f);
    }
    __syncthreads();
    if (t < D_) {
        float s = 0.f;
        #pragma unroll
        for (int j = 0; j < I_; j++) s += amean[j] * vs[j * 132 + t];
        vmean[t] = s;
    }
    __syncthreads();
    if (t < F_) {  // meta = vmean @ out_w^T + out_b
        float s = pob[t];
        #pragma unroll 4
        for (int f = 0; f < D_; f++) s += vmean[f] * pow_[t * D_ + f];
        d_meta[(size_t)bp * F_ + t] = s;
    }
}

// ---------------- Kernel D: MPA per b + v2 + score base ----------------
__global__ void k_mpa(const float* __restrict__ miw, const float* __restrict__ mib,
                      const float* __restrict__ mow, const float* __restrict__ mob,
                      const float* __restrict__ qiw, const float* __restrict__ qib,
                      const float* __restrict__ qow, const float* __restrict__ qob,
                      const float* __restrict__ query, const float* __restrict__ sw,
                      const float* __restrict__ sb) {
    int b = blockIdx.x;
    int t = threadIdx.x;  // 0..127
    __shared__ float xs[I_ * D_];
    __shared__ float qs[I_ * 132], ks[I_ * 132], vs[I_ * 132];
    __shared__ float attn[I_ * I_];
    __shared__ float amean[I_];
    __shared__ float vmean[D_], v1s[F_], mps[F_], t1s[F_], v2s[F_];
    __shared__ float red[128];

    const float* xg = d_meta + (size_t)b * I_ * D_;
    for (int idx = t; idx < I_ * D_; idx += 128) xs[idx] = xg[idx];
    __syncthreads();

    for (int part = 0; part < 3; part++) {
        const float* wrow = miw + (size_t)(part * F_ + t) * F_;
        float acc[I_];
        #pragma unroll
        for (int i = 0; i < I_; i++) acc[i] = 0.f;
        for (int d = 0; d < D_; d++) {
            float w = wrow[d];
            #pragma unroll
            for (int i = 0; i < I_; i++) acc[i] += xs[i * D_ + d] * w;
        }
        float bb = mib[part * F_ + t];
        float* dst = part == 0 ? qs : (part == 1 ? ks : vs);
        #pragma unroll
        for (int i = 0; i < I_; i++) dst[i * 132 + t] = acc[i] + bb;
    }
    __syncthreads();

    for (int pr = t; pr < 256; pr += 128) {
        int i = pr >> 4, j = pr & 15;
        float s = 0.f;
        #pragma unroll 8
        for (int f = 0; f < D_; f++) s += qs[i * 132 + f] * ks[j * 132 + f];
        attn[pr] = s * INV_SQRT_F;
    }
    __syncthreads();
    if (t < I_) {
        float m = attn[t * 16];
        for (int j = 1; j < 16; j++) m = fmaxf(m, attn[t * 16 + j]);
        float sum = 0.f;
        for (int j = 0; j < 16; j++) { float e = __expf(attn[t * 16 + j] - m); attn[t * 16 + j] = e; sum += e; }
        float inv = 1.f / sum;
        for (int j = 0; j < 16; j++) attn[t * 16 + j] *= inv;
    }
    __syncthreads();
    if (t < I_) {
        float s = 0.f;
        for (int i = 0; i < 16; i++) s += attn[i * 16 + t];
        amean[t] = s * (1.f / 16.f);
    }
    __syncthreads();
    {   // vmean and mean over P of meta
        float s = 0.f;
        #pragma unroll
        for (int j = 0; j < I_; j++) s += amean[j] * vs[j * 132 + t];
        vmean[t] = s;
        float sm = 0.f;
        #pragma unroll
        for (int i = 0; i < I_; i++) sm += xs[i * D_ + t];
        mps[t] = sm * (1.f / 16.f);
    }
    __syncthreads();
    {   // v1 = vmean @ mpa_out_w^T + b ; t1 = meanP @ qia_v_w^T + qia_v_b
        float s = mob[t];
        #pragma unroll 4
        for (int f = 0; f < D_; f++) s += vmean[f] * mow[t * D_ + f];
        v1s[t] = s;
        float s2 = qib[2 * F_ + t];
        const float* wrow = qiw + (size_t)(2 * F_ + t) * F_;
        #pragma unroll 4
        for (int f = 0; f < F_; f++) s2 += mps[f] * wrow[f];
        t1s[t] = s2;
    }
    __syncthreads();
    {   // v2 = t1 @ qia_out_w^T + b
        float s = qob[t];
        #pragma unroll 4
        for (int f = 0; f < F_; f++) s += t1s[f] * qow[t * F_ + f];
        v2s[t] = s;
    }
    __syncthreads();
    // base[b] = q.w0 + v1.w1 + v2.w2 + score_b
    float pb = query[b * D_ + t] * sw[t] + v1s[t] * sw[D_ + t] + v2s[t] * sw[D_ + F_ + t];
    red[t] = pb;
    __syncthreads();
    for (int off = 64; off > 0; off >>= 1) {
        if (t < off) red[t] += red[t + off];
        __syncthreads();
    }
    if (t == 0) d_base[b] = red[0] + sb[0];
}

// ---------------- Kernel F: candidate scores ----------------
// block = (b,p); 8 warps, warp = one candidate per iteration (float4 dot of 128)
__global__ void k_score(const float* __restrict__ cand, const int* __restrict__ clen,
                        const float* __restrict__ sw) {
    int bp = blockIdx.x;
    int b = bp >> 4;
    int warp = threadIdx.x >> 5, lane = threadIdx.x & 31;
    __shared__ float4 ws[32];
    __shared__ float sbase;
    if (threadIdx.x < 32) ws[threadIdx.x] = ((const float4*)(sw + D_ + 2 * F_))[threadIdx.x];
    if (threadIdx.x == 0) sbase = d_base[b];
    int len = clen[bp];
    __syncthreads();
    const float4* cbase = (const float4*)cand + (size_t)bp * C_ * 32;
    float4 w = ws[lane];
    float bse = sbase;
    for (int c = warp; c < C_; c += 8) {
        float4 v = cbase[c * 32 + lane];
        float s = v.x * w.x + v.y * w.y + v.z * w.z + v.w * w.w;
        #pragma unroll
        for (int off = 16; off; off >>= 1) s += __shfl_xor_sync(0xffffffffu, s, off);
        if (lane == 0) d_scores[(size_t)bp * C_ + c] = (c < len) ? (s + bse) : NEG;
    }
}

// ---------------- Kernel G: softmax over P*C per b ----------------
__global__ void k_softmax(float* __restrict__ out) {
    int b = blockIdx.x;
    const float* s = d_scores + (size_t)b * (P_ * C_);
    float* o = out + (size_t)b * (P_ * C_);
    int t = threadIdx.x;  // 0..1023
    __shared__ float red[1024];
    float m = -1e30f;
    for (int i = t; i < P_ * C_; i += 1024) m = fmaxf(m, s[i]);
    red[t] = m;
    __syncthreads();
    for (int off = 512; off > 0; off >>= 1) {
        if (t < off) red[t] = fmaxf(red[t], red[t + off]);
        __syncthreads();
    }
    float mx = red[0];
    __syncthreads();
    float sum = 0.f;
    for (int i = t; i < P_ * C_; i += 1024) sum += __expf(s[i] - mx);
    red[t] = sum;
    __syncthreads();
    for (int off = 512; off > 0; off >>= 1) {
        if (t < off) red[t] += red[t + off];
        __syncthreads();
    }
    float inv = 1.f / red[0];
    for (int i = t; i < P_ * C_; i += 1024) o[i] = __expf(s[i] - mx) * inv;
}

// ---------------- launch ----------------
extern "C" void kernel_launch(void* const* d_in, const int* in_sizes, int n_in,
                              void* d_out, int out_size) {
    const float* query    = (const float*)d_in[0];
    const float* path_emb = (const float*)d_in[1];
    const int*   path_len = (const int*)d_in[2];
    const float* cand_emb = (const float*)d_in[3];
    const int*   cand_len = (const int*)d_in[4];
    const float* conv_w   = (const float*)d_in[5];
    const float* conv_b   = (const float*)d_in[6];
    const float* pia_in_w = (const float*)d_in[7];
    const float* pia_in_b = (const float*)d_in[8];
    const float* pia_out_w= (const float*)d_in[9];
    const float* pia_out_b= (const float*)d_in[10];
    const float* mpa_in_w = (const float*)d_in[11];
    const float* mpa_in_b = (const float*)d_in[12];
    const float* mpa_out_w= (const float*)d_in[13];
    const float* mpa_out_b= (const float*)d_in[14];
    const float* qia_in_w = (const float*)d_in[15];
    const float* qia_in_b = (const float*)d_in[16];
    const float* qia_out_w= (const float*)d_in[17];
    const float* qia_out_b= (const float*)d_in[18];
    const float* score_w  = (const float*)d_in[19];
    const float* score_b  = (const float*)d_in[20];
    float* out = (float*)d_out;

    k_mean<<<BPI, 128>>>(path_emb, path_len);
    k_fold<<<384, 128>>>(pia_in_w, pia_in_b, conv_w, conv_b);
    k_pia<<<BP, 384>>>(pia_out_w, pia_out_b);
    k_mpa<<<B_, 128>>>(mpa_in_w, mpa_in_b, mpa_out_w, mpa_out_b,
                       qia_in_w, qia_in_b, qia_out_w, qia_out_b,
                       query, score_w, score_b);
    k_score<<<BP, 256>>>(cand_emb, cand_len, score_w);
    k_softmax<<<B_, 1024>>>(out);
}

// round 8
// speedup vs baseline: 1.3251x; 1.3127x over previous
#include <cuda_runtime.h>
#include <cuda_bf16.h>
#include <cstdint>

#define B_ 16
#define P_ 16
#define I_ 16
#define L_ 64
#define D_ 128
#define F_ 128
#define C_ 1024
#define BPI 4096
#define BP 256
#define NEG (-1000000000.0f)
#define INV_SQRT_F 0.08838834764831845f

// ---------------- scratch (no allocations allowed) ----------------
__device__ float d_meanx[BPI * D_];       // (B,P,I,D) masked means
__device__ float d_WcT[D_ * 384];         // folded PIA qkv weight, transposed [d][t]
__device__ float d_bc[384];               // folded PIA qkv bias
__device__ float d_powT[D_ * F_];         // pia_out_w transposed [f][t]
__device__ float d_miwT[D_ * 384];        // mpa_in_w transposed [d][t]
__device__ float d_mowT[D_ * F_];         // mpa_out_w transposed [f][t]
__device__ float d_qiwVT[F_ * F_];        // qia_in_w rows [2F..3F) transposed [f][t]
__device__ float d_qowT[F_ * F_];         // qia_out_w transposed [f][t]
__device__ float d_meta[BP * F_];         // (B,P,F)
__device__ float d_base[B_];              // per-b score base
__device__ float d_scores[B_ * P_ * C_];  // raw masked logits

// ---------------- Kernel A: masked mean over L ----------------
__global__ void k_mean(const float* __restrict__ pe, const int* __restrict__ plen) {
    int bpi = blockIdx.x;
    int len = plen[bpi];
    int warp = threadIdx.x >> 5, lane = threadIdx.x & 31;
    const float4* base = (const float4*)pe + (size_t)bpi * (L_ * 32);
    float4 acc = make_float4(0.f, 0.f, 0.f, 0.f);
    for (int l = warp; l < len; l += 4) {
        float4 v = base[l * 32 + lane];
        acc.x += v.x; acc.y += v.y; acc.z += v.z; acc.w += v.w;
    }
    __shared__ float4 sred[128];
    sred[threadIdx.x] = acc;
    __syncthreads();
    if (warp == 0) {
        float4 a = sred[lane], b = sred[32 + lane], c = sred[64 + lane], d = sred[96 + lane];
        float inv = 1.0f / (float)len;
        float4 r;
        r.x = (a.x + b.x + c.x + d.x) * inv;
        r.y = (a.y + b.y + c.y + d.y) * inv;
        r.z = (a.z + b.z + c.z + d.z) * inv;
        r.w = (a.w + b.w + c.w + d.w) * inv;
        ((float4*)d_meanx)[(size_t)bpi * 32 + lane] = r;
    }
}

// ---------------- Kernel B: fold conv into pia_in ----------------
__global__ void k_fold(const float* __restrict__ piw, const float* __restrict__ pib,
                       const float* __restrict__ cw, const float* __restrict__ cb) {
    int t = blockIdx.x;      // 0..383
    int d = threadIdx.x;     // 0..127
    float s = 0.f;
    #pragma unroll 4
    for (int f = 0; f < F_; f++) s += piw[t * F_ + f] * cw[f * D_ + d];
    d_WcT[d * 384 + t] = s;
    __shared__ float sb[128];
    sb[d] = piw[t * F_ + d] * cb[d];
    __syncthreads();
    for (int off = 64; off > 0; off >>= 1) {
        if (d < off) sb[d] += sb[d + off];
        __syncthreads();
    }
    if (d == 0) d_bc[t] = pib[t] + sb[0];
}

// ---------------- Kernel B2: transpose all per-thread-row weights ----------------
// block = output row t (0..383); thread = d/f (0..127). Reads coalesced.
__global__ void k_prep(const float* __restrict__ pow_, const float* __restrict__ miw,
                       const float* __restrict__ mow, const float* __restrict__ qiw,
                       const float* __restrict__ qow) {
    int t = blockIdx.x;   // 0..383
    int d = threadIdx.x;  // 0..127
    d_miwT[d * 384 + t] = miw[t * F_ + d];
    if (t < F_) {
        d_powT[d * F_ + t] = pow_[t * D_ + d];
        d_mowT[d * F_ + t] = mow[t * D_ + d];
        d_qiwVT[d * F_ + t] = qiw[(size_t)(2 * F_ + t) * F_ + d];
        d_qowT[d * F_ + t] = qow[t * F_ + d];
    }
}

// ---------------- Kernel C: PIA attention per (b,p) ----------------
__global__ void k_pia(const float* __restrict__ pob) {
    int bp = blockIdx.x;
    int t = threadIdx.x;  // 0..383
    __shared__ float xs[I_ * D_];
    __shared__ float qs[I_ * 132], ks[I_ * 132], vs[I_ * 132];
    __shared__ float attn[I_ * I_];
    __shared__ float amean[I_];
    __shared__ float vmean[D_];

    const float* xg = d_meanx + (size_t)bp * I_ * D_;
    for (int idx = t; idx < I_ * D_; idx += 384) xs[idx] = xg[idx];
    __syncthreads();

    float acc[I_];
    #pragma unroll
    for (int i = 0; i < I_; i++) acc[i] = 0.f;
    for (int d = 0; d < D_; d++) {
        float w = d_WcT[d * 384 + t];  // coalesced
        #pragma unroll
        for (int i = 0; i < I_; i++) acc[i] += xs[i * D_ + d] * w;
    }
    {
        float b = d_bc[t];
        float* dst = (t < 128) ? qs : (t < 256 ? ks : vs);
        int f = t & 127;
        #pragma unroll
        for (int i = 0; i < I_; i++) dst[i * 132 + f] = acc[i] + b;
    }
    __syncthreads();

    if (t < 256) {
        int i = t >> 4, j = t & 15;
        float s = 0.f;
        #pragma unroll 8
        for (int f = 0; f < D_; f++) s += qs[i * 132 + f] * ks[j * 132 + f];
        attn[t] = s * INV_SQRT_F;
    }
    __syncthreads();
    if (t < I_) {
        float m = attn[t * 16];
        for (int j = 1; j < 16; j++) m = fmaxf(m, attn[t * 16 + j]);
        float sum = 0.f;
        for (int j = 0; j < 16; j++) { float e = __expf(attn[t * 16 + j] - m); attn[t * 16 + j] = e; sum += e; }
        float inv = 1.f / sum;
        for (int j = 0; j < 16; j++) attn[t * 16 + j] *= inv;
    }
    __syncthreads();
    if (t < I_) {
        float s = 0.f;
        for (int i = 0; i < 16; i++) s += attn[i * 16 + t];
        amean[t] = s * (1.f / 16.f);
    }
    __syncthreads();
    if (t < D_) {
        float s = 0.f;
        #pragma unroll
        for (int j = 0; j < I_; j++) s += amean[j] * vs[j * 132 + t];
        vmean[t] = s;
    }
    __syncthreads();
    if (t < F_) {  // meta = vmean @ out_w^T + out_b, via transposed weight (coalesced)
        float s = pob[t];
        #pragma unroll 4
        for (int f = 0; f < D_; f++) s += vmean[f] * d_powT[f * F_ + t];
        d_meta[(size_t)bp * F_ + t] = s;
    }
}

// ---------------- Kernel D: MPA per b + v2 + score base (384 threads, coalesced) ----------------
__global__ void k_mpa(const float* __restrict__ mib, const float* __restrict__ mob,
                      const float* __restrict__ qib, const float* __restrict__ qob,
                      const float* __restrict__ query, const float* __restrict__ sw,
                      const float* __restrict__ sb) {
    int b = blockIdx.x;
    int t = threadIdx.x;  // 0..383
    __shared__ float xs[I_ * D_];
    __shared__ float qs[I_ * 132], ks[I_ * 132], vs[I_ * 132];
    __shared__ float attn[I_ * I_];
    __shared__ float amean[I_];
    __shared__ float vmean[D_], v1s[F_], mps[F_], t1s[F_], v2s[F_];
    __shared__ float red[128];

    const float* xg = d_meta + (size_t)b * I_ * D_;
    for (int idx = t; idx < I_ * D_; idx += 384) xs[idx] = xg[idx];
    __syncthreads();

    // qkv: one thread per output (coalesced transposed weight)
    float acc[I_];
    #pragma unroll
    for (int i = 0; i < I_; i++) acc[i] = 0.f;
    for (int d = 0; d < D_; d++) {
        float w = d_miwT[d * 384 + t];
        #pragma unroll
        for (int i = 0; i < I_; i++) acc[i] += xs[i * D_ + d] * w;
    }
    {
        float bb = mib[t];
        float* dst = (t < 128) ? qs : (t < 256 ? ks : vs);
        int f = t & 127;
        #pragma unroll
        for (int i = 0; i < I_; i++) dst[i * 132 + f] = acc[i] + bb;
    }
    __syncthreads();

    if (t < 256) {
        int i = t >> 4, j = t & 15;
        float s = 0.f;
        #pragma unroll 8
        for (int f = 0; f < D_; f++) s += qs[i * 132 + f] * ks[j * 132 + f];
        attn[t] = s * INV_SQRT_F;
    }
    __syncthreads();
    if (t < I_) {
        float m = attn[t * 16];
        for (int j = 1; j < 16; j++) m = fmaxf(m, attn[t * 16 + j]);
        float sum = 0.f;
        for (int j = 0; j < 16; j++) { float e = __expf(attn[t * 16 + j] - m); attn[t * 16 + j] = e; sum += e; }
        float inv = 1.f / sum;
        for (int j = 0; j < 16; j++) attn[t * 16 + j] *= inv;
    }
    __syncthreads();
    if (t < I_) {
        float s = 0.f;
        for (int i = 0; i < 16; i++) s += attn[i * 16 + t];
        amean[t] = s * (1.f / 16.f);
    }
    __syncthreads();
    if (t < D_) {  // vmean and mean over P of meta
        float s = 0.f;
        #pragma unroll
        for (int j = 0; j < I_; j++) s += amean[j] * vs[j * 132 + t];
        vmean[t] = s;
        float sm = 0.f;
        #pragma unroll
        for (int i = 0; i < I_; i++) sm += xs[i * D_ + t];
        mps[t] = sm * (1.f / 16.f);
    }
    __syncthreads();
    if (t < F_) {  // v1 and t1, coalesced transposed weights
        float s = mob[t];
        #pragma unroll 4
        for (int f = 0; f < D_; f++) s += vmean[f] * d_mowT[f * F_ + t];
        v1s[t] = s;
        float s2 = qib[2 * F_ + t];
        #pragma unroll 4
        for (int f = 0; f < F_; f++) s2 += mps[f] * d_qiwVT[f * F_ + t];
        t1s[t] = s2;
    }
    __syncthreads();
    if (t < F_) {
        float s = qob[t];
        #pragma unroll 4
        for (int f = 0; f < F_; f++) s += t1s[f] * d_qowT[f * F_ + t];
        v2s[t] = s;
    }
    __syncthreads();
    if (t < 128) {
        float pb = query[b * D_ + t] * sw[t] + v1s[t] * sw[D_ + t] + v2s[t] * sw[D_ + F_ + t];
        red[t] = pb;
    }
    __syncthreads();
    for (int off = 64; off > 0; off >>= 1) {
        if (t < off) red[t] += red[t + off];
        __syncthreads();
    }
    if (t == 0) d_base[b] = red[0] + sb[0];
}

// ---------------- Kernel F: candidate scores ----------------
// grid (BP, 4): block covers 256 candidates of one (b,p); warp per candidate.
__global__ void k_score(const float* __restrict__ cand, const int* __restrict__ clen,
                        const float* __restrict__ sw) {
    int bp = blockIdx.x;
    int b = bp >> 4;
    int cbeg = blockIdx.y * (C_ / 4);
    int warp = threadIdx.x >> 5, lane = threadIdx.x & 31;
    __shared__ float4 ws[32];
    __shared__ float sbase;
    if (threadIdx.x < 32) ws[threadIdx.x] = ((const float4*)(sw + D_ + 2 * F_))[threadIdx.x];
    if (threadIdx.x == 0) sbase = d_base[b];
    int len = clen[bp];
    __syncthreads();
    const float4* cbase = (const float4*)cand + (size_t)bp * C_ * 32;
    float4 w = ws[lane];
    float bse = sbase;
    #pragma unroll 4
    for (int cc = warp; cc < C_ / 4; cc += 8) {
        int c = cbeg + cc;
        float4 v = cbase[c * 32 + lane];
        float s = v.x * w.x + v.y * w.y + v.z * w.z + v.w * w.w;
        #pragma unroll
        for (int off = 16; off; off >>= 1) s += __shfl_xor_sync(0xffffffffu, s, off);
        if (lane == 0) d_scores[(size_t)bp * C_ + c] = (c < len) ? (s + bse) : NEG;
    }
}

// ---------------- Kernel G: softmax over P*C per b ----------------
__global__ void k_softmax(float* __restrict__ out) {
    int b = blockIdx.x;
    const float* s = d_scores + (size_t)b * (P_ * C_);
    float* o = out + (size_t)b * (P_ * C_);
    int t = threadIdx.x;  // 0..1023
    __shared__ float red[1024];
    float m = -1e30f;
    for (int i = t; i < P_ * C_; i += 1024) m = fmaxf(m, s[i]);
    red[t] = m;
    __syncthreads();
    for (int off = 512; off > 0; off >>= 1) {
        if (t < off) red[t] = fmaxf(red[t], red[t + off]);
        __syncthreads();
    }
    float mx = red[0];
    __syncthreads();
    float sum = 0.f;
    for (int i = t; i < P_ * C_; i += 1024) sum += __expf(s[i] - mx);
    red[t] = sum;
    __syncthreads();
    for (int off = 512; off > 0; off >>= 1) {
        if (t < off) red[t] += red[t + off];
        __syncthreads();
    }
    float inv = 1.f / red[0];
    for (int i = t; i < P_ * C_; i += 1024) o[i] = __expf(s[i] - mx) * inv;
}

// ---------------- launch ----------------
extern "C" void kernel_launch(void* const* d_in, const int* in_sizes, int n_in,
                              void* d_out, int out_size) {
    const float* query    = (const float*)d_in[0];
    const float* path_emb = (const float*)d_in[1];
    const int*   path_len = (const int*)d_in[2];
    const float* cand_emb = (const float*)d_in[3];
    const int*   cand_len = (const int*)d_in[4];
    const float* conv_w   = (const float*)d_in[5];
    const float* conv_b   = (const float*)d_in[6];
    const float* pia_in_w = (const float*)d_in[7];
    const float* pia_in_b = (const float*)d_in[8];
    const float* pia_out_w= (const float*)d_in[9];
    const float* pia_out_b= (const float*)d_in[10];
    const float* mpa_in_w = (const float*)d_in[11];
    const float* mpa_in_b = (const float*)d_in[12];
    const float* mpa_out_w= (const float*)d_in[13];
    const float* mpa_out_b= (const float*)d_in[14];
    const float* qia_in_w = (const float*)d_in[15];
    const float* qia_in_b = (const float*)d_in[16];
    const float* qia_out_w= (const float*)d_in[17];
    const float* qia_out_b= (const float*)d_in[18];
    const float* score_w  = (const float*)d_in[19];
    const float* score_b  = (const float*)d_in[20];
    float* out = (float*)d_out;

    k_mean<<<BPI, 128>>>(path_emb, path_len);
    k_fold<<<384, 128>>>(pia_in_w, pia_in_b, conv_w, conv_b);
    k_prep<<<384, 128>>>(pia_out_w, mpa_in_w, mpa_out_w, qia_in_w, qia_out_w);
    k_pia<<<BP, 384>>>(pia_out_b);
    k_mpa<<<B_, 384>>>(mpa_in_b, mpa_out_b, qia_in_b, qia_out_b,
                       query, score_w, score_b);
    k_score<<<dim3(BP, 4), 256>>>(cand_emb, cand_len, score_w);
    k_softmax<<<B_, 1024>>>(out);
}